// round 15
// baseline (speedup 1.0000x reference)
#include <cuda_runtime.h>
#include <cuda_bf16.h>
#include <math.h>
#include <stdint.h>

#define NU 200000
#define NI 200000
#define D  128
#define B  4096
#define KP  512     // pred K
#define KFP 32      // pred K frags (K/16)
#define KR  272     // RNN K: [x(128) | h(128) | t(1) | pad(15)]
#define KFR 17      // RNN K frags

// ---- output layout (flattened tuple, row-major) ----
#define OFF_PRED       0
#define OFF_TARGET     (B*2*D)
#define OFF_UPD_USER   (OFF_TARGET + B*2*D)
#define OFF_USER_EMB   (OFF_UPD_USER + B*D)
#define OFF_UPD_ITEM   (OFF_USER_EMB + B*D)
#define OFF_ITEM_EMB   (OFF_UPD_ITEM + B*D)
#define OFF_DYN_USER   (OFF_ITEM_EMB + B*D)
#define OFF_DYN_ITEM   (OFF_DYN_USER + NU*D)
#define OFF_ISNEW_U    (OFF_DYN_ITEM + NI*D)
#define OFF_ISNEW_I    (OFF_ISNEW_U + NU)

typedef __nv_bfloat16 bf16;

// ---- device scratch: operands in m16n8k16 FRAGMENT layout, hi/lo bf16 ----
__device__ __align__(16) bf16 g_XpH[B * KP];
__device__ __align__(16) bf16 g_XpL[B * KP];
__device__ __align__(16) bf16 g_XuH[B * KR];
__device__ __align__(16) bf16 g_XuL[B * KR];
__device__ __align__(16) bf16 g_XiH[B * KR];
__device__ __align__(16) bf16 g_XiL[B * KR];
__device__ __align__(16) bf16 g_WpH[256 * KP];
__device__ __align__(16) bf16 g_WpL[256 * KP];
__device__ __align__(16) bf16 g_WuH[D * KR];
__device__ __align__(16) bf16 g_WuL[D * KR];
__device__ __align__(16) bf16 g_WvH[D * KR];
__device__ __align__(16) bf16 g_WvL[D * KR];
__device__ float g_bu[D];
__device__ float g_bi[D];
// winner sentinel: 0 = none, else b+1. Zero-init; scatter resets consumed entries.
__device__ int g_winner_u[NU];
__device__ int g_winner_i[NI];

// ---- dependency counters (zero-init; reset by last scatter CTA each run) ----
__device__ int g_c_gather;
__device__ int g_c_winner;
__device__ int g_c_prep;
__device__ int g_c_mma;
__device__ int g_c_copy;
__device__ int g_c_scatter;

// role sizes / targets
#define N_CFRONT 64
#define N_GATHER 256      // 16 batch rows per CTA
#define N_WINNER 16
#define N_PREP   325      // 256 pred + 68 rnn + 1 bias
#define N_MMA    256      // 128 pred + 64 user + 64 item
#define N_SCAT   64
#define N_CBACK  960
#define NCOPY    (N_CFRONT + N_CBACK)
#define GRID     (N_CFRONT + N_GATHER + N_WINNER + N_PREP + N_MMA + N_SCAT + N_CBACK)

// ---- release / acquire over counters ----
__device__ __forceinline__ void signal_cnt(int* c) {
    __threadfence();
    __syncthreads();
    if (threadIdx.x == 0) atomicAdd(c, 1);
}
__device__ __forceinline__ void wait_cnt(int* c, int target) {
    if (threadIdx.x == 0)
        while (*(volatile int*)c < target) __nanosleep(64);
    __syncthreads();
    __threadfence();
}

// m16n8k16 A-fragment offset (bf16 units) for even k (pair-aligned)
__device__ __forceinline__ int a_off(int m, int k0, int KF) {
    int mf = m >> 4, r = m & 15, g = r & 7, h = r >> 3;
    int kf = k0 >> 4, kl = k0 & 15, t = (kl >> 1) & 3, reg = h + 2 * (kl >> 3);
    return ((mf * KF + kf) << 8) + (((g << 2) + t) << 3) + reg * 2;
}
// B-fragment offset
__device__ __forceinline__ int b_off(int n, int k0, int KF) {
    int nf = n >> 3, g = n & 7;
    int kf = k0 >> 4, kl = k0 & 15, t = (kl >> 1) & 3, reg = kl >> 3;
    return ((nf * KF + kf) << 7) + (((g << 2) + t) << 2) + reg * 2;
}

__device__ __forceinline__ void mma_bf16(float* c, uint4 a, uint2 b) {
    asm volatile(
        "mma.sync.aligned.m16n8k16.row.col.f32.bf16.bf16.f32 "
        "{%0,%1,%2,%3},{%4,%5,%6,%7},{%8,%9},{%0,%1,%2,%3};"
        : "+f"(c[0]), "+f"(c[1]), "+f"(c[2]), "+f"(c[3])
        : "r"(a.x), "r"(a.y), "r"(a.z), "r"(a.w), "r"(b.x), "r"(b.y));
}

// ---- copy machinery: MLP=8 + streaming hints ----
#define N4_U    (NU * D / 4)
#define N4_I    (NI * D / 4)
#define N4_ISU  (NU / 4)
#define N4_ISI  (NI / 4)

__device__ __forceinline__ void copy_range(const float4* __restrict__ src,
                                           float4* __restrict__ dst,
                                           int hi, int cta, int ncta) {
    int stride = ncta * 256;
    int i = cta * 256 + (int)threadIdx.x;
    for (; i + 7 * stride < hi; i += 8 * stride) {
        float4 v0 = __ldcs(src + i);
        float4 v1 = __ldcs(src + i + stride);
        float4 v2 = __ldcs(src + i + 2 * stride);
        float4 v3 = __ldcs(src + i + 3 * stride);
        float4 v4 = __ldcs(src + i + 4 * stride);
        float4 v5 = __ldcs(src + i + 5 * stride);
        float4 v6 = __ldcs(src + i + 6 * stride);
        float4 v7 = __ldcs(src + i + 7 * stride);
        __stcs(dst + i,              v0); __stcs(dst + i + stride,     v1);
        __stcs(dst + i + 2 * stride, v2); __stcs(dst + i + 3 * stride, v3);
        __stcs(dst + i + 4 * stride, v4); __stcs(dst + i + 5 * stride, v5);
        __stcs(dst + i + 6 * stride, v6); __stcs(dst + i + 7 * stride, v7);
    }
    for (; i < hi; i += stride) __stcs(dst + i, __ldcs(src + i));
}

// split v into hi/lo bf16, pack with lane-partner (d^1) and store pair (even d)
__device__ __forceinline__ void frag_pair_A(bf16* Hd, bf16* Ld, int m, int kbase,
                                            int d, int KF, float v) {
    bf16 h = __float2bfloat16(v);
    bf16 l = __float2bfloat16(v - __bfloat162float(h));
    uint32_t hu = __bfloat16_as_ushort(h), lu = __bfloat16_as_ushort(l);
    uint32_t ph = __shfl_xor_sync(0xffffffffu, hu, 1);
    uint32_t pl = __shfl_xor_sync(0xffffffffu, lu, 1);
    if (!(d & 1)) {
        int off = a_off(m, kbase + d, KF);
        *(uint32_t*)(Hd + off) = hu | (ph << 16);
        *(uint32_t*)(Ld + off) = lu | (pl << 16);
    }
}

// write hi/lo pair into B fragment layout
__device__ __forceinline__ void frag_pair_B(bf16* Hd, bf16* Ld, int n, int k0,
                                            int KF, float w0, float w1) {
    bf16 h0 = __float2bfloat16(w0), h1 = __float2bfloat16(w1);
    bf16 l0 = __float2bfloat16(w0 - __bfloat162float(h0));
    bf16 l1 = __float2bfloat16(w1 - __bfloat162float(h1));
    int off = b_off(n, k0, KF);
    *(uint32_t*)(Hd + off) = (uint32_t)__bfloat16_as_ushort(h0) |
                             ((uint32_t)__bfloat16_as_ushort(h1) << 16);
    *(uint32_t*)(Ld + off) = (uint32_t)__bfloat16_as_ushort(l0) |
                             ((uint32_t)__bfloat16_as_ushort(l1) << 16);
}

// ---------------------------------------------------------------------------
// split-precision bf16 HMMA GEMM: 256-thr CTA = 8 warps (4M x 2N),
// CTA tile 128x64, warp tile 32x32; 3 segments (AhBh, AhBl, AlBh) in fp32.
template <int KF, bool TANH>
__device__ __forceinline__ void mma_gemm(const bf16* __restrict__ AH, const bf16* __restrict__ AL,
                                         const bf16* __restrict__ BH, const bf16* __restrict__ BL,
                                         const float* __restrict__ bias,
                                         float* __restrict__ C, int ldc, int m0, int n0) {
    int tid = threadIdx.x;
    int wid = tid >> 5, lane = tid & 31;
    int m0w = m0 + (wid >> 1) * 32;
    int n0w = n0 + (wid & 1) * 32;
    int mf0 = m0w >> 4, nf0 = n0w >> 3;
    int aslot = lane * 8, bslot = lane * 4;

    float acc[2][4][4];
    #pragma unroll
    for (int i = 0; i < 2; i++)
        #pragma unroll
        for (int j = 0; j < 4; j++)
            #pragma unroll
            for (int q = 0; q < 4; q++) acc[i][j][q] = 0.f;

    #pragma unroll
    for (int seg = 0; seg < 3; seg++) {
        const bf16* Ap = (seg < 2) ? AH : AL;
        const bf16* Bp = (seg == 1) ? BL : BH;
        #pragma unroll 2
        for (int kf = 0; kf < KF; kf++) {
            uint4 a[2];
            uint2 b[4];
            #pragma unroll
            for (int i = 0; i < 2; i++)
                a[i] = *(const uint4*)(Ap + (((mf0 + i) * KF + kf) << 8) + aslot);
            #pragma unroll
            for (int j = 0; j < 4; j++)
                b[j] = *(const uint2*)(Bp + (((nf0 + j) * KF + kf) << 7) + bslot);
            #pragma unroll
            for (int i = 0; i < 2; i++)
                #pragma unroll
                for (int j = 0; j < 4; j++)
                    mma_bf16(acc[i][j], a[i], b[j]);
        }
    }

    int g = lane >> 2, t = lane & 3;
    #pragma unroll
    for (int i = 0; i < 2; i++) {
        #pragma unroll
        for (int j = 0; j < 4; j++) {
            int n = n0w + j * 8 + t * 2;
            float b0 = bias[n], b1 = bias[n + 1];
            float c0 = acc[i][j][0] + b0, c1 = acc[i][j][1] + b1;
            float c2 = acc[i][j][2] + b0, c3 = acc[i][j][3] + b1;
            if (TANH) { c0 = tanhf(c0); c1 = tanhf(c1); c2 = tanhf(c2); c3 = tanhf(c3); }
            int mrow = m0w + i * 16 + g;
            *(float2*)&C[(size_t)mrow * ldc + n]       = make_float2(c0, c1);
            *(float2*)&C[(size_t)(mrow + 8) * ldc + n] = make_float2(c2, c3);
        }
    }
}

// ---------------------------------------------------------------------------
__global__ void __launch_bounds__(256, 3) mega_kernel(
        const int* __restrict__ uid, const int* __restrict__ pid,
        const int* __restrict__ iid,
        const float* __restrict__ t_item, const float* __restrict__ t_user,
        const float* __restrict__ dynU, const float* __restrict__ dynI,
        const float* __restrict__ isU, const float* __restrict__ isI,
        const float* __restrict__ statU, const float* __restrict__ statI,
        const float* __restrict__ initU, const float* __restrict__ initI,
        const float* __restrict__ tdW, const float* __restrict__ tdb,
        const float* __restrict__ uWih, const float* __restrict__ uWhh,
        const float* __restrict__ ubih, const float* __restrict__ ubhh,
        const float* __restrict__ iWih, const float* __restrict__ iWhh,
        const float* __restrict__ ibih, const float* __restrict__ ibhh,
        const float* __restrict__ predW, const float* __restrict__ predb,
        float* __restrict__ out) {
    int bx = blockIdx.x;
    int tid = threadIdx.x;

    // ---------------- copy role (front + back pool, no waits) ----------------
    int cidx = -1;
    if (bx < N_CFRONT) cidx = bx;
    else if (bx >= GRID - N_CBACK) cidx = N_CFRONT + (bx - (GRID - N_CBACK));
    if (cidx >= 0) {
        copy_range((const float4*)dynU, (float4*)(out + OFF_DYN_USER), N4_U, cidx, NCOPY);
        copy_range((const float4*)dynI, (float4*)(out + OFF_DYN_ITEM), N4_I, cidx, NCOPY);
        copy_range((const float4*)isU,  (float4*)(out + OFF_ISNEW_U),  N4_ISU, cidx, NCOPY);
        copy_range((const float4*)isI,  (float4*)(out + OFF_ISNEW_I),  N4_ISI, cidx, NCOPY);
        signal_cnt(&g_c_copy);
        return;
    }
    bx -= N_CFRONT;

    // ---------------- gather: 16 batch rows per CTA ----------------
    if (bx < N_GATHER) {
        int d = tid & 127;
        for (int r = 0; r < 8; r++) {
            int b = bx * 16 + r * 2 + (tid >> 7);
            int u = uid[b], p = pid[b], it = iid[b];
            float ti = t_item[b], tu = t_user[b];
            float fu = isU[u], fi = isI[it], fp = isI[p];

            float ue = fu * initU[d] + dynU[(long)u * D + d];
            float ie = fi * initI[d] + dynI[(long)it * D + d];
            float pe = fp * initI[d] + dynI[(long)p * D + d];
            float su = statU[(long)u * D + d];
            float si = statI[(long)it * D + d];
            float ps = statI[(long)p * D + d];

            out[OFF_USER_EMB + b * D + d] = ue;
            out[OFF_ITEM_EMB + b * D + d] = ie;
            out[OFF_TARGET + b * 2 * D + d]     = ie;
            out[OFF_TARGET + b * 2 * D + D + d] = si;

            float proj = ue * (1.f + ti * tdW[d] + tdb[d]);
            frag_pair_A(g_XpH, g_XpL, b, 0,   d, KFP, proj);
            frag_pair_A(g_XpH, g_XpL, b, 128, d, KFP, pe);
            frag_pair_A(g_XpH, g_XpL, b, 256, d, KFP, ps);
            frag_pair_A(g_XpH, g_XpL, b, 384, d, KFP, su);
            frag_pair_A(g_XuH, g_XuL, b, 0,   d, KFR, ie);
            frag_pair_A(g_XuH, g_XuL, b, 128, d, KFR, ue);
            frag_pair_A(g_XiH, g_XiL, b, 0,   d, KFR, ue);
            frag_pair_A(g_XiH, g_XiL, b, 128, d, KFR, ie);
            if (d < 8) {   // tail pairs k=256..271: (t,0) then zeros
                int k0 = 256 + 2 * d;
                uint32_t uh = 0, ul = 0, ih = 0, il = 0;
                if (d == 0) {
                    bf16 h = __float2bfloat16(ti);
                    bf16 l = __float2bfloat16(ti - __bfloat162float(h));
                    uh = __bfloat16_as_ushort(h); ul = __bfloat16_as_ushort(l);
                    h = __float2bfloat16(tu);
                    l = __float2bfloat16(tu - __bfloat162float(h));
                    ih = __bfloat16_as_ushort(h); il = __bfloat16_as_ushort(l);
                }
                int off = a_off(b, k0, KFR);
                *(uint32_t*)(g_XuH + off) = uh; *(uint32_t*)(g_XuL + off) = ul;
                *(uint32_t*)(g_XiH + off) = ih; *(uint32_t*)(g_XiL + off) = il;
            }
        }
        signal_cnt(&g_c_gather);
        return;
    }
    bx -= N_GATHER;

    // ---------------- winner: last occurrence wins (sentinel b+1) ----------------
    if (bx < N_WINNER) {
        int b = bx * 256 + tid;
        atomicMax(&g_winner_u[uid[b]], b + 1);
        atomicMax(&g_winner_i[iid[b]], b + 1);
        signal_cnt(&g_c_winner);
        return;
    }
    bx -= N_WINNER;

    // ---------------- prep: weights to fragment layout + fused bias ----------------
    if (bx < N_PREP) {
        if (bx < 256) {              // pred W pairs
            int pidx = bx * 256 + tid;
            int n = pidx >> 8, k0 = (pidx & 255) * 2;
            frag_pair_B(g_WpH, g_WpL, n, k0, KFP,
                        predW[n * KP + k0], predW[n * KP + k0 + 1]);
        } else if (bx < 324) {       // RNN W pairs (both cells)
            int pidx = (bx - 256) * 256 + tid;   // < 17408
            int n = pidx / (KR / 2), kp = pidx % (KR / 2);
            int k0 = kp * 2;
            float wu[2], wv[2];
            #pragma unroll
            for (int e = 0; e < 2; e++) {
                int k = k0 + e;
                float a = 0.f, c = 0.f;
                if (k < 128)      { a = uWih[n * 129 + k];         c = iWih[n * 129 + k]; }
                else if (k < 256) { a = uWhh[n * 128 + (k - 128)]; c = iWhh[n * 128 + (k - 128)]; }
                else if (k == 256){ a = uWih[n * 129 + 128];       c = iWih[n * 129 + 128]; }
                wu[e] = a; wv[e] = c;
            }
            frag_pair_B(g_WuH, g_WuL, n, k0, KFR, wu[0], wu[1]);
            frag_pair_B(g_WvH, g_WvL, n, k0, KFR, wv[0], wv[1]);
        } else {                     // biases
            if (tid < D) {
                g_bu[tid] = ubih[tid] + ubhh[tid];
                g_bi[tid] = ibih[tid] + ibhh[tid];
            }
        }
        signal_cnt(&g_c_prep);
        return;
    }
    bx -= N_PREP;

    // ---------------- MMA (waits gather + prep) ----------------
    if (bx < N_MMA) {
        wait_cnt(&g_c_gather, N_GATHER);
        wait_cnt(&g_c_prep, N_PREP);
        if (bx < 128) {              // pred: 32 M x 4 N (CTA tile 128x64)
            int m0 = (bx & 31) * 128, n0 = (bx >> 5) * 64;
            mma_gemm<KFP, false>(g_XpH, g_XpL, g_WpH, g_WpL, predb,
                                 out + OFF_PRED, 256, m0, n0);
        } else if (bx < 192) {       // RNN user: 32 M x 2 N
            int r = bx - 128;
            int m0 = (r & 31) * 128, n0 = (r >> 5) * 64;
            mma_gemm<KFR, true>(g_XuH, g_XuL, g_WuH, g_WuL, g_bu,
                                out + OFF_UPD_USER, 128, m0, n0);
        } else {                     // RNN item
            int r = bx - 192;
            int m0 = (r & 31) * 128, n0 = (r >> 5) * 64;
            mma_gemm<KFR, true>(g_XiH, g_XiL, g_WvH, g_WvL, g_bi,
                                out + OFF_UPD_ITEM, 128, m0, n0);
        }
        signal_cnt(&g_c_mma);
        return;
    }
    bx -= N_MMA;

    // ---------------- scatter (waits mma + copy + winner) ----------------
    {
        wait_cnt(&g_c_mma, N_MMA);
        wait_cnt(&g_c_winner, N_WINNER);
        wait_cnt(&g_c_copy, NCOPY);
        // counter reset for next graph replay: last scatter CTA to pass its waits
        if (tid == 0) {
            int old = atomicAdd(&g_c_scatter, 1);
            if (old == N_SCAT - 1) {
                g_c_gather = 0; g_c_winner = 0; g_c_prep = 0;
                g_c_mma = 0; g_c_copy = 0; g_c_scatter = 0;
                __threadfence();
            }
        }
        int wid = tid >> 5, lane = tid & 31;
        for (int s = 0; s < 16; s++) {
            int gw = (bx * 8 + wid) * 16 + s;     // 0..8191
            if (gw < B) {
                int id = uid[gw];
                if (lane == 0) out[OFF_ISNEW_U + id] = 0.f;
                if (g_winner_u[id] == gw + 1) {
                    float4 v = *(const float4*)(out + OFF_UPD_USER + (long)gw * D + lane * 4);
                    *(float4*)(out + OFF_DYN_USER + (long)id * D + lane * 4) = v;
                    if (lane == 0) g_winner_u[id] = 0;
                }
            } else {
                int b = gw - B;
                int id = iid[b];
                if (lane == 0) out[OFF_ISNEW_I + id] = 0.f;
                if (g_winner_i[id] == b + 1) {
                    float4 v = *(const float4*)(out + OFF_UPD_ITEM + (long)b * D + lane * 4);
                    *(float4*)(out + OFF_DYN_ITEM + (long)id * D + lane * 4) = v;
                    if (lane == 0) g_winner_i[id] = 0;
                }
            }
        }
    }
}

// ---------------------------------------------------------------------------
extern "C" void kernel_launch(void* const* d_in, const int* in_sizes, int n_in,
                              void* d_out, int out_size) {
    const int*   uid   = (const int*)d_in[0];
    const int*   pid   = (const int*)d_in[1];
    const int*   iid   = (const int*)d_in[2];
    const float* tItem = (const float*)d_in[3];
    const float* tUser = (const float*)d_in[4];
    const float* dynU  = (const float*)d_in[5];
    const float* dynI  = (const float*)d_in[6];
    const float* isU   = (const float*)d_in[7];
    const float* isI   = (const float*)d_in[8];
    const float* statU = (const float*)d_in[9];
    const float* statI = (const float*)d_in[10];
    const float* initU = (const float*)d_in[11];
    const float* initI = (const float*)d_in[12];
    const float* uWih  = (const float*)d_in[13];
    const float* uWhh  = (const float*)d_in[14];
    const float* ubih  = (const float*)d_in[15];
    const float* ubhh  = (const float*)d_in[16];
    const float* iWih  = (const float*)d_in[17];
    const float* iWhh  = (const float*)d_in[18];
    const float* ibih  = (const float*)d_in[19];
    const float* ibhh  = (const float*)d_in[20];
    const float* predW = (const float*)d_in[21];
    const float* predb = (const float*)d_in[22];
    const float* tdW   = (const float*)d_in[23];
    const float* tdb   = (const float*)d_in[24];
    float* out = (float*)d_out;

    mega_kernel<<<GRID, 256>>>(uid, pid, iid, tItem, tUser, dynU, dynI,
                               isU, isI, statU, statI, initU, initI,
                               tdW, tdb, uWih, uWhh, ubih, ubhh,
                               iWih, iWhh, ibih, ibhh, predW, predb, out);
}

// round 17
// speedup vs baseline: 1.1317x; 1.1317x over previous
#include <cuda_runtime.h>
#include <cuda_bf16.h>
#include <math.h>
#include <stdint.h>

#define NU 200000
#define NI 200000
#define D  128
#define B  4096
#define KP  512     // pred K
#define KFP 32      // pred K frags (K/16)
#define KR  272     // RNN K: [x(128) | h(128) | t(1) | pad(15)]
#define KFR 17      // RNN K frags

// ---- output layout (flattened tuple, row-major) ----
#define OFF_PRED       0
#define OFF_TARGET     (B*2*D)
#define OFF_UPD_USER   (OFF_TARGET + B*2*D)
#define OFF_USER_EMB   (OFF_UPD_USER + B*D)
#define OFF_UPD_ITEM   (OFF_USER_EMB + B*D)
#define OFF_ITEM_EMB   (OFF_UPD_ITEM + B*D)
#define OFF_DYN_USER   (OFF_ITEM_EMB + B*D)
#define OFF_DYN_ITEM   (OFF_DYN_USER + NU*D)
#define OFF_ISNEW_U    (OFF_DYN_ITEM + NI*D)
#define OFF_ISNEW_I    (OFF_ISNEW_U + NU)

typedef __nv_bfloat16 bf16;

// ---- device scratch: operands in m16n8k16 FRAGMENT layout, hi/lo bf16 ----
__device__ __align__(16) bf16 g_XpH[B * KP];
__device__ __align__(16) bf16 g_XpL[B * KP];
__device__ __align__(16) bf16 g_XuH[B * KR];
__device__ __align__(16) bf16 g_XuL[B * KR];
__device__ __align__(16) bf16 g_XiH[B * KR];
__device__ __align__(16) bf16 g_XiL[B * KR];
__device__ __align__(16) bf16 g_WpH[256 * KP];
__device__ __align__(16) bf16 g_WpL[256 * KP];
__device__ __align__(16) bf16 g_WuH[D * KR];
__device__ __align__(16) bf16 g_WuL[D * KR];
__device__ __align__(16) bf16 g_WvH[D * KR];
__device__ __align__(16) bf16 g_WvL[D * KR];
__device__ float g_bu[D];
__device__ float g_bi[D];
// winner sentinel: 0 = none, else b+1. Zero-init; scatter resets consumed entries.
__device__ int g_winner_u[NU];
__device__ int g_winner_i[NI];
// work-stealing chunk queues (zero-init; scatter resets for next graph replay)
__device__ int g_q1;
__device__ int g_q2;

// m16n8k16 A-fragment offset (bf16 units) for even k (pair-aligned)
__device__ __forceinline__ int a_off(int m, int k0, int KF) {
    int mf = m >> 4, r = m & 15, g = r & 7, h = r >> 3;
    int kf = k0 >> 4, kl = k0 & 15, t = (kl >> 1) & 3, reg = h + 2 * (kl >> 3);
    return ((mf * KF + kf) << 8) + (((g << 2) + t) << 3) + reg * 2;
}
// B-fragment offset
__device__ __forceinline__ int b_off(int n, int k0, int KF) {
    int nf = n >> 3, g = n & 7;
    int kf = k0 >> 4, kl = k0 & 15, t = (kl >> 1) & 3, reg = kl >> 3;
    return ((nf * KF + kf) << 7) + (((g << 2) + t) << 2) + reg * 2;
}

__device__ __forceinline__ void mma_bf16(float* c, uint4 a, uint2 b) {
    asm volatile(
        "mma.sync.aligned.m16n8k16.row.col.f32.bf16.bf16.f32 "
        "{%0,%1,%2,%3},{%4,%5,%6,%7},{%8,%9},{%0,%1,%2,%3};"
        : "+f"(c[0]), "+f"(c[1]), "+f"(c[2]), "+f"(c[3])
        : "r"(a.x), "r"(a.y), "r"(a.z), "r"(a.w), "r"(b.x), "r"(b.y));
}

// ---- copy machinery: MLP=8 + streaming hints + work-stealing chunks ----
#define N4_U    (NU * D / 4)     // 6.4M float4
#define N4_I    (NI * D / 4)
#define N4_ISU  (NU / 4)
#define N4_ISI  (NI / 4)
#define CHUNK   8192             // float4 per stolen chunk (128 KB)
#define C1_U    ((N4_U + CHUNK - 1) / CHUNK)      // 782
#define C_ISU   ((N4_ISU + CHUNK - 1) / CHUNK)    // 7
#define C_ISI   ((N4_ISI + CHUNK - 1) / CHUNK)    // 7
#define C1_TOT  (C1_U + C_ISU + C_ISI)
#define C2_TOT  ((N4_I + CHUNK - 1) / CHUNK)      // 782

#define P1_COPY 1536
#define P2_COPY 768

template <int BT>
__device__ __forceinline__ void copy_chunk(const float4* __restrict__ src,
                                           float4* __restrict__ dst,
                                           int base, int n) {
    int end = min(base + CHUNK, n);
    int i = base + (int)threadIdx.x;
    for (; i + 7 * BT < end; i += 8 * BT) {
        float4 v0 = __ldcs(src + i);
        float4 v1 = __ldcs(src + i + BT);
        float4 v2 = __ldcs(src + i + 2 * BT);
        float4 v3 = __ldcs(src + i + 3 * BT);
        float4 v4 = __ldcs(src + i + 4 * BT);
        float4 v5 = __ldcs(src + i + 5 * BT);
        float4 v6 = __ldcs(src + i + 6 * BT);
        float4 v7 = __ldcs(src + i + 7 * BT);
        __stcs(dst + i,          v0); __stcs(dst + i + BT,     v1);
        __stcs(dst + i + 2 * BT, v2); __stcs(dst + i + 3 * BT, v3);
        __stcs(dst + i + 4 * BT, v4); __stcs(dst + i + 5 * BT, v5);
        __stcs(dst + i + 6 * BT, v6); __stcs(dst + i + 7 * BT, v7);
    }
    for (; i < end; i += BT) __stcs(dst + i, __ldcs(src + i));
}

// split v into hi/lo bf16, pack with lane-partner (d^1) and store pair (even d)
__device__ __forceinline__ void frag_pair_A(bf16* Hd, bf16* Ld, int m, int kbase,
                                            int d, int KF, float v) {
    bf16 h = __float2bfloat16(v);
    bf16 l = __float2bfloat16(v - __bfloat162float(h));
    uint32_t hu = __bfloat16_as_ushort(h), lu = __bfloat16_as_ushort(l);
    uint32_t ph = __shfl_xor_sync(0xffffffffu, hu, 1);
    uint32_t pl = __shfl_xor_sync(0xffffffffu, lu, 1);
    if (!(d & 1)) {
        int off = a_off(m, kbase + d, KF);
        *(uint32_t*)(Hd + off) = hu | (ph << 16);
        *(uint32_t*)(Ld + off) = lu | (pl << 16);
    }
}

// write hi/lo pair into B fragment layout
__device__ __forceinline__ void frag_pair_B(bf16* Hd, bf16* Ld, int n, int k0,
                                            int KF, float w0, float w1) {
    bf16 h0 = __float2bfloat16(w0), h1 = __float2bfloat16(w1);
    bf16 l0 = __float2bfloat16(w0 - __bfloat162float(h0));
    bf16 l1 = __float2bfloat16(w1 - __bfloat162float(h1));
    int off = b_off(n, k0, KF);
    *(uint32_t*)(Hd + off) = (uint32_t)__bfloat16_as_ushort(h0) |
                             ((uint32_t)__bfloat16_as_ushort(h1) << 16);
    *(uint32_t*)(Ld + off) = (uint32_t)__bfloat16_as_ushort(l0) |
                             ((uint32_t)__bfloat16_as_ushort(l1) << 16);
}

// ---------------------------------------------------------------------------
// phase1: [copy (steal dynU+flags) | gather | winner | prep]
#define PREP_PRED 512        // 65536 pred-W pairs / 128
#define PREP_RNN  137        // 17408 rnn pairs / 128 + bias block
__global__ void __launch_bounds__(128) phase1_kernel(
        const int* __restrict__ uid, const int* __restrict__ pid,
        const int* __restrict__ iid,
        const float* __restrict__ t_item, const float* __restrict__ t_user,
        const float* __restrict__ dynU, const float* __restrict__ dynI,
        const float* __restrict__ isU, const float* __restrict__ isI,
        const float* __restrict__ statU, const float* __restrict__ statI,
        const float* __restrict__ initU, const float* __restrict__ initI,
        const float* __restrict__ tdW, const float* __restrict__ tdb,
        const float* __restrict__ uWih, const float* __restrict__ uWhh,
        const float* __restrict__ ubih, const float* __restrict__ ubhh,
        const float* __restrict__ iWih, const float* __restrict__ iWhh,
        const float* __restrict__ ibih, const float* __restrict__ ibhh,
        const float* __restrict__ predW,
        float* __restrict__ out) {
    int bx = blockIdx.x;

    if (bx < P1_COPY) {
        __shared__ int sc;
        for (;;) {
            if (threadIdx.x == 0) sc = atomicAdd(&g_q1, 1);
            __syncthreads();
            int c = sc;
            __syncthreads();
            if (c >= C1_TOT) break;
            if (c < C1_U)
                copy_chunk<128>((const float4*)dynU, (float4*)(out + OFF_DYN_USER),
                                c * CHUNK, N4_U);
            else if (c < C1_U + C_ISU)
                copy_chunk<128>((const float4*)isU, (float4*)(out + OFF_ISNEW_U),
                                (c - C1_U) * CHUNK, N4_ISU);
            else
                copy_chunk<128>((const float4*)isI, (float4*)(out + OFF_ISNEW_I),
                                (c - C1_U - C_ISU) * CHUNK, N4_ISI);
        }
        return;
    }
    bx -= P1_COPY;

    if (bx < B) {
        int b = bx;
        int d = threadIdx.x;
        int u = uid[b], p = pid[b], it = iid[b];
        float ti = t_item[b], tu = t_user[b];
        float fu = isU[u], fi = isI[it], fp = isI[p];

        float ue = fu * initU[d] + dynU[(long)u * D + d];
        float ie = fi * initI[d] + dynI[(long)it * D + d];
        float pe = fp * initI[d] + dynI[(long)p * D + d];
        float su = statU[(long)u * D + d];
        float si = statI[(long)it * D + d];
        float ps = statI[(long)p * D + d];

        out[OFF_USER_EMB + b * D + d] = ue;
        out[OFF_ITEM_EMB + b * D + d] = ie;
        out[OFF_TARGET + b * 2 * D + d]     = ie;
        out[OFF_TARGET + b * 2 * D + D + d] = si;

        float proj = ue * (1.f + ti * tdW[d] + tdb[d]);
        frag_pair_A(g_XpH, g_XpL, b, 0,   d, KFP, proj);
        frag_pair_A(g_XpH, g_XpL, b, 128, d, KFP, pe);
        frag_pair_A(g_XpH, g_XpL, b, 256, d, KFP, ps);
        frag_pair_A(g_XpH, g_XpL, b, 384, d, KFP, su);
        frag_pair_A(g_XuH, g_XuL, b, 0,   d, KFR, ie);
        frag_pair_A(g_XuH, g_XuL, b, 128, d, KFR, ue);
        frag_pair_A(g_XiH, g_XiL, b, 0,   d, KFR, ue);
        frag_pair_A(g_XiH, g_XiL, b, 128, d, KFR, ie);
        if (d < 8) {   // tail pairs k=256..271: (t,0) then zeros
            int k0 = 256 + 2 * d;
            uint32_t uh = 0, ul = 0, ih = 0, il = 0;
            if (d == 0) {
                bf16 h = __float2bfloat16(ti);
                bf16 l = __float2bfloat16(ti - __bfloat162float(h));
                uh = __bfloat16_as_ushort(h); ul = __bfloat16_as_ushort(l);
                h = __float2bfloat16(tu);
                l = __float2bfloat16(tu - __bfloat162float(h));
                ih = __bfloat16_as_ushort(h); il = __bfloat16_as_ushort(l);
            }
            int off = a_off(b, k0, KFR);
            *(uint32_t*)(g_XuH + off) = uh; *(uint32_t*)(g_XuL + off) = ul;
            *(uint32_t*)(g_XiH + off) = ih; *(uint32_t*)(g_XiL + off) = il;
        }
        return;
    }
    bx -= B;

    if (bx < B / 128) {
        int b = bx * 128 + threadIdx.x;
        atomicMax(&g_winner_u[uid[b]], b + 1);
        atomicMax(&g_winner_i[iid[b]], b + 1);
        return;
    }
    bx -= B / 128;

    if (bx < PREP_PRED) {   // pred W: pair per thread
        int pidx = bx * 128 + threadIdx.x;
        int n = pidx >> 8, k0 = (pidx & 255) * 2;
        frag_pair_B(g_WpH, g_WpL, n, k0, KFP,
                    predW[n * KP + k0], predW[n * KP + k0 + 1]);
        return;
    }
    bx -= PREP_PRED;

    {   // RNN W pairs (both cells) + bias
        int pidx = bx * 128 + threadIdx.x;
        if (pidx < D * (KR / 2)) {
            int n = pidx / (KR / 2), kp = pidx % (KR / 2);
            int k0 = kp * 2;
            float wu[2], wv[2];
            #pragma unroll
            for (int e = 0; e < 2; e++) {
                int k = k0 + e;
                float a = 0.f, c = 0.f;
                if (k < 128)      { a = uWih[n * 129 + k];         c = iWih[n * 129 + k]; }
                else if (k < 256) { a = uWhh[n * 128 + (k - 128)]; c = iWhh[n * 128 + (k - 128)]; }
                else if (k == 256){ a = uWih[n * 129 + 128];       c = iWih[n * 129 + 128]; }
                wu[e] = a; wv[e] = c;
            }
            frag_pair_B(g_WuH, g_WuL, n, k0, KFR, wu[0], wu[1]);
            frag_pair_B(g_WvH, g_WvL, n, k0, KFR, wv[0], wv[1]);
        }
        if (bx == PREP_RNN - 1 && threadIdx.x < D) {
            int i = threadIdx.x;
            g_bu[i] = ubih[i] + ubhh[i];
            g_bi[i] = ibih[i] + ibhh[i];
        }
    }
}
#define P1_GRID (P1_COPY + B + B/128 + PREP_PRED + PREP_RNN)

// ---------------------------------------------------------------------------
// split-precision bf16 HMMA GEMM: 256-thr CTA = 8 warps (4M x 2N),
// CTA tile 128x64, warp tile 32x32 (acc 32 regs); 3 segments in fp32.
template <int KF, bool TANH>
__device__ __forceinline__ void mma_gemm(const bf16* __restrict__ AH, const bf16* __restrict__ AL,
                                         const bf16* __restrict__ BH, const bf16* __restrict__ BL,
                                         const float* __restrict__ bias,
                                         float* __restrict__ C, int ldc, int m0, int n0) {
    int tid = threadIdx.x;
    int wid = tid >> 5, lane = tid & 31;
    int m0w = m0 + (wid >> 1) * 32;
    int n0w = n0 + (wid & 1) * 32;
    int mf0 = m0w >> 4, nf0 = n0w >> 3;
    int aslot = lane * 8, bslot = lane * 4;

    float acc[2][4][4];
    #pragma unroll
    for (int i = 0; i < 2; i++)
        #pragma unroll
        for (int j = 0; j < 4; j++)
            #pragma unroll
            for (int q = 0; q < 4; q++) acc[i][j][q] = 0.f;

    #pragma unroll
    for (int seg = 0; seg < 3; seg++) {
        const bf16* Ap = (seg < 2) ? AH : AL;
        const bf16* Bp = (seg == 1) ? BL : BH;
        #pragma unroll 2
        for (int kf = 0; kf < KF; kf++) {
            uint4 a[2];
            uint2 b[4];
            #pragma unroll
            for (int i = 0; i < 2; i++)
                a[i] = *(const uint4*)(Ap + (((mf0 + i) * KF + kf) << 8) + aslot);
            #pragma unroll
            for (int j = 0; j < 4; j++)
                b[j] = *(const uint2*)(Bp + (((nf0 + j) * KF + kf) << 7) + bslot);
            #pragma unroll
            for (int i = 0; i < 2; i++)
                #pragma unroll
                for (int j = 0; j < 4; j++)
                    mma_bf16(acc[i][j], a[i], b[j]);
        }
    }

    int g = lane >> 2, t = lane & 3;
    #pragma unroll
    for (int i = 0; i < 2; i++) {
        #pragma unroll
        for (int j = 0; j < 4; j++) {
            int n = n0w + j * 8 + t * 2;
            float b0 = bias[n], b1 = bias[n + 1];
            float c0 = acc[i][j][0] + b0, c1 = acc[i][j][1] + b1;
            float c2 = acc[i][j][2] + b0, c3 = acc[i][j][3] + b1;
            if (TANH) { c0 = tanhf(c0); c1 = tanhf(c1); c2 = tanhf(c2); c3 = tanhf(c3); }
            int mrow = m0w + i * 16 + g;
            *(float2*)&C[(size_t)mrow * ldc + n]       = make_float2(c0, c1);
            *(float2*)&C[(size_t)(mrow + 8) * ldc + n] = make_float2(c2, c3);
        }
    }
}

// ---------------------------------------------------------------------------
// phase2, 256 thr/CTA, <=64 regs (4 CTAs/SM): [MMA 256 | copy steal dynI 768]
__global__ void __launch_bounds__(256, 4) phase2_kernel(
        const float* __restrict__ dynI,
        const float* __restrict__ predb,
        float* __restrict__ out) {
    int bx = blockIdx.x;

    if (bx < 128) {      // pred: 32 M-tiles x 4 N-tiles (CTA tile 128x64)
        int m0 = (bx & 31) * 128, n0 = (bx >> 5) * 64;
        mma_gemm<KFP, false>(g_XpH, g_XpL, g_WpH, g_WpL, predb,
                             out + OFF_PRED, 256, m0, n0);
        return;
    }
    bx -= 128;

    if (bx < 64) {       // RNN user: 32 M x 2 N
        int m0 = (bx & 31) * 128, n0 = (bx >> 5) * 64;
        mma_gemm<KFR, true>(g_XuH, g_XuL, g_WuH, g_WuL, g_bu,
                            out + OFF_UPD_USER, 128, m0, n0);
        return;
    }
    bx -= 64;

    if (bx < 64) {       // RNN item
        int m0 = (bx & 31) * 128, n0 = (bx >> 5) * 64;
        mma_gemm<KFR, true>(g_XiH, g_XiL, g_WvH, g_WvL, g_bi,
                            out + OFF_UPD_ITEM, 128, m0, n0);
        return;
    }

    {   // copy dynI via work-stealing
        __shared__ int sc;
        for (;;) {
            if (threadIdx.x == 0) sc = atomicAdd(&g_q2, 1);
            __syncthreads();
            int c = sc;
            __syncthreads();
            if (c >= C2_TOT) break;
            copy_chunk<256>((const float4*)dynI, (float4*)(out + OFF_DYN_ITEM),
                            c * CHUNK, N4_I);
        }
    }
}
#define P2_GRID (128 + 64 + 64 + P2_COPY)

// ---------------------------------------------------------------------------
// patch winner rows, zero is_new for batch ids, reset winner + queue state
__global__ void scatter_kernel(const int* __restrict__ uid, const int* __restrict__ iid,
                               float* __restrict__ out) {
    if (blockIdx.x == 0 && threadIdx.x == 0) { g_q1 = 0; g_q2 = 0; }
    int gw = blockIdx.x * 8 + (threadIdx.x >> 5);
    int lane = threadIdx.x & 31;
    if (gw < B) {
        int id = uid[gw];
        if (lane == 0) out[OFF_ISNEW_U + id] = 0.f;
        if (g_winner_u[id] == gw + 1) {
            float4 v = *(const float4*)(out + OFF_UPD_USER + (long)gw * D + lane * 4);
            *(float4*)(out + OFF_DYN_USER + (long)id * D + lane * 4) = v;
            if (lane == 0) g_winner_u[id] = 0;
        }
    } else {
        int b = gw - B;
        if (b < B) {
            int id = iid[b];
            if (lane == 0) out[OFF_ISNEW_I + id] = 0.f;
            if (g_winner_i[id] == b + 1) {
                float4 v = *(const float4*)(out + OFF_UPD_ITEM + (long)b * D + lane * 4);
                *(float4*)(out + OFF_DYN_ITEM + (long)id * D + lane * 4) = v;
                if (lane == 0) g_winner_i[id] = 0;
            }
        }
    }
}

// ---------------------------------------------------------------------------
extern "C" void kernel_launch(void* const* d_in, const int* in_sizes, int n_in,
                              void* d_out, int out_size) {
    const int*   uid   = (const int*)d_in[0];
    const int*   pid   = (const int*)d_in[1];
    const int*   iid   = (const int*)d_in[2];
    const float* tItem = (const float*)d_in[3];
    const float* tUser = (const float*)d_in[4];
    const float* dynU  = (const float*)d_in[5];
    const float* dynI  = (const float*)d_in[6];
    const float* isU   = (const float*)d_in[7];
    const float* isI   = (const float*)d_in[8];
    const float* statU = (const float*)d_in[9];
    const float* statI = (const float*)d_in[10];
    const float* initU = (const float*)d_in[11];
    const float* initI = (const float*)d_in[12];
    const float* uWih  = (const float*)d_in[13];
    const float* uWhh  = (const float*)d_in[14];
    const float* ubih  = (const float*)d_in[15];
    const float* ubhh  = (const float*)d_in[16];
    const float* iWih  = (const float*)d_in[17];
    const float* iWhh  = (const float*)d_in[18];
    const float* ibih  = (const float*)d_in[19];
    const float* ibhh  = (const float*)d_in[20];
    const float* predW = (const float*)d_in[21];
    const float* predb = (const float*)d_in[22];
    const float* tdW   = (const float*)d_in[23];
    const float* tdb   = (const float*)d_in[24];
    float* out = (float*)d_out;

    phase1_kernel<<<P1_GRID, 128>>>(uid, pid, iid, tItem, tUser, dynU, dynI,
                                    isU, isI, statU, statI, initU, initI,
                                    tdW, tdb, uWih, uWhh, ubih, ubhh,
                                    iWih, iWhh, ibih, ibhh, predW, out);
    phase2_kernel<<<P2_GRID, 256>>>(dynI, predb, out);
    scatter_kernel<<<(2 * B) / 8, 256>>>(uid, iid, out);
}